// round 4
// baseline (speedup 1.0000x reference)
#include <cuda_runtime.h>
#include <cuda_fp16.h>
#include <math.h>

#define BATCH 8
#define N     2048
#define TPB   256
#define RPC   32                    // rows per CTA in big kernels
#define NBLK  (N / RPC)             // 64
#define GRID_BIG (BATCH * NBLK)     // 512
#define INVL  20.0f                 // 1/lambda
#define NITER 10
#define RPW   4                     // rows per warp (iter kernel): 8 warps * 4 = 32 rows/CTA
#define ITER_SMEM ((2048 + 8 * 2048) * 4)   // tau (8KB) + per-warp cp slices (64KB)

// scratch (__device__ globals; no allocation allowed)
__device__ __half g_P[(size_t)BATCH * N * N];    // 67 MB: Q = fp16(P0 * s2 * t1), L2-resident
__device__ float  g_m[BATCH * N];                // row maxes of A*INVL
__device__ float  g_s[BATCH * N];                // s^(10)
__device__ float  g_acc[NITER + 1][BATCH * N];   // column accumulators per iteration

__global__ void zero_kernel() {
    int idx = blockIdx.x * TPB + threadIdx.x;    // zero acc[1..10]
    (&g_acc[1][0])[idx] = 0.0f;
}

__device__ __forceinline__ void warp_red2(float& l0, float& l1) {
    #pragma unroll
    for (int o = 16; o; o >>= 1) {
        l0 += __shfl_xor_sync(0xffffffffu, l0, o);
        l1 += __shfl_xor_sync(0xffffffffu, l1, o);
    }
}

// K1 = iteration 1 (fp32 from A): m_i = rowmax; s1 = 1/rowsum(P0); acc1 = colsum(P0 s1)
__global__ void __launch_bounds__(TPB) k1_kernel(const float* __restrict__ A) {
    const int blk = blockIdx.x, b = blk / NBLK, rb = blk % NBLK;
    const int tid = threadIdx.x, wid = tid >> 5, lane = tid & 31;
    const int col = tid * 8;
    const size_t base = (size_t)b * N * N;
    __shared__ float redA[8][2], redB[8][2];
    float cp[8] = {0, 0, 0, 0, 0, 0, 0, 0};

    #pragma unroll 1
    for (int p = 0; p < RPC / 2; p++) {
        const int r0 = rb * RPC + 2 * p;
        const float4* a0p = (const float4*)(A + base + (size_t)r0 * N + col);
        const float4* a1p = (const float4*)(A + base + (size_t)(r0 + 1) * N + col);
        float4 x0 = a0p[0], x1 = a0p[1], y0 = a1p[0], y1 = a1p[1];
        float a0[8] = {x0.x, x0.y, x0.z, x0.w, x1.x, x1.y, x1.z, x1.w};
        float a1[8] = {y0.x, y0.y, y0.z, y0.w, y1.x, y1.y, y1.z, y1.w};
        float m0 = -INFINITY, m1 = -INFINITY;
        #pragma unroll
        for (int k = 0; k < 8; k++) {
            a0[k] *= INVL; a1[k] *= INVL;
            m0 = fmaxf(m0, a0[k]); m1 = fmaxf(m1, a1[k]);
        }
        #pragma unroll
        for (int o = 16; o; o >>= 1) {
            m0 = fmaxf(m0, __shfl_xor_sync(0xffffffffu, m0, o));
            m1 = fmaxf(m1, __shfl_xor_sync(0xffffffffu, m1, o));
        }
        if (lane == 0) { redA[wid][0] = m0; redA[wid][1] = m1; }
        __syncthreads();
        m0 = redA[0][0]; m1 = redA[0][1];
        #pragma unroll
        for (int w = 1; w < 8; w++) { m0 = fmaxf(m0, redA[w][0]); m1 = fmaxf(m1, redA[w][1]); }

        float e0[8], e1[8], l0 = 0.0f, l1 = 0.0f;
        #pragma unroll
        for (int k = 0; k < 8; k++) {
            e0[k] = __expf(a0[k] - m0); e1[k] = __expf(a1[k] - m1);
            l0 += e0[k]; l1 += e1[k];
        }
        warp_red2(l0, l1);
        if (lane == 0) { redB[wid][0] = l0; redB[wid][1] = l1; }
        __syncthreads();
        l0 = redB[0][0]; l1 = redB[0][1];
        #pragma unroll
        for (int w = 1; w < 8; w++) { l0 += redB[w][0]; l1 += redB[w][1]; }
        const float s0 = 1.0f / l0, s1 = 1.0f / l1;
        if (tid == 0) { g_m[b * N + r0] = m0; g_m[b * N + r0 + 1] = m1; }
        #pragma unroll
        for (int k = 0; k < 8; k++) {
            cp[k] = fmaf(e0[k], s0, cp[k]);
            cp[k] = fmaf(e1[k], s1, cp[k]);
        }
    }
    float* acc = &g_acc[1][b * N + col];
    #pragma unroll
    for (int k = 0; k < 8; k++) atomicAdd(acc + k, cp[k]);
}

// K2 = iteration 2 (fp32 from A) + write Q = fp16(P0 s2 t1); acc2 = colsum(Q)
__global__ void __launch_bounds__(TPB) k2_kernel(const float* __restrict__ A) {
    const int blk = blockIdx.x, b = blk / NBLK, rb = blk % NBLK;
    const int tid = threadIdx.x, wid = tid >> 5, lane = tid & 31;
    const int col = tid * 8;
    const size_t base = (size_t)b * N * N;
    __shared__ float red[2][8][2];

    const float* a1p = &g_acc[1][b * N + col];
    float tv[8], cp[8] = {0, 0, 0, 0, 0, 0, 0, 0};
    #pragma unroll
    for (int j = 0; j < 8; j++) tv[j] = 1.0f / a1p[j];

    #pragma unroll 1
    for (int p = 0; p < RPC / 2; p++) {
        const int r0 = rb * RPC + 2 * p;
        const float4* p0 = (const float4*)(A + base + (size_t)r0 * N + col);
        const float4* p1 = (const float4*)(A + base + (size_t)(r0 + 1) * N + col);
        float4 x0 = p0[0], x1 = p0[1], y0 = p1[0], y1 = p1[1];
        float a0[8] = {x0.x, x0.y, x0.z, x0.w, x1.x, x1.y, x1.z, x1.w};
        float a1[8] = {y0.x, y0.y, y0.z, y0.w, y1.x, y1.y, y1.z, y1.w};
        const float m0 = g_m[b * N + r0], m1 = g_m[b * N + r0 + 1];
        float e0[8], e1[8], l0 = 0.0f, l1 = 0.0f;
        #pragma unroll
        for (int k = 0; k < 8; k++) {
            e0[k] = __expf(fmaf(a0[k], INVL, -m0)) * tv[k];   // P0 * t1
            e1[k] = __expf(fmaf(a1[k], INVL, -m1)) * tv[k];
            l0 += e0[k]; l1 += e1[k];
        }
        warp_red2(l0, l1);
        if (lane == 0) { red[p & 1][wid][0] = l0; red[p & 1][wid][1] = l1; }
        __syncthreads();
        l0 = red[p & 1][0][0]; l1 = red[p & 1][0][1];
        #pragma unroll
        for (int w = 1; w < 8; w++) { l0 += red[p & 1][w][0]; l1 += red[p & 1][w][1]; }
        const float s0 = 1.0f / l0, s1 = 1.0f / l1;   // s2 rows

        float q0[8], q1[8];
        #pragma unroll
        for (int k = 0; k < 8; k++) {
            q0[k] = e0[k] * s0;  q1[k] = e1[k] * s1;   // Q entries (row sums == 1)
            cp[k] += q0[k] + q1[k];
        }
        uint4 w0, w1;
        __half2* h0 = reinterpret_cast<__half2*>(&w0);
        __half2* h1 = reinterpret_cast<__half2*>(&w1);
        #pragma unroll
        for (int j = 0; j < 4; j++) {
            h0[j] = __floats2half2_rn(q0[2 * j], q0[2 * j + 1]);
            h1[j] = __floats2half2_rn(q1[2 * j], q1[2 * j + 1]);
        }
        *(uint4*)(g_P + base + (size_t)r0 * N + col) = w0;
        *(uint4*)(g_P + base + (size_t)(r0 + 1) * N + col) = w1;
    }
    float* acc = &g_acc[2][b * N + col];
    #pragma unroll
    for (int k = 0; k < 8; k++) atomicAdd(acc + k, cp[k]);
}

// K3..K9 = iterations 3..9 on fp16 Q. Warp-per-row, barrier-free main loop.
// smem: s_tau[2048] (swizzled) + per-warp cp slices s_cp[8][2048] (swizzled).
// Swizzle: (chunk c, half p, lane l) -> float index (64*c + 32*p + l)*4 .. +3
__global__ void __launch_bounds__(TPB, 3) iter_kernel(int k) {
    extern __shared__ float sm[];
    float* s_tau = sm;             // 2048 floats
    float* s_cp  = sm + 2048;      // 8 * 2048 floats

    const int blk = blockIdx.x, b = blk / NBLK, rb = blk % NBLK;
    const int tid = threadIdx.x, wid = tid >> 5, lane = tid & 31;
    const int c = tid >> 5, l = tid & 31;            // thread's column group
    const int col = c * 256 + l * 8;                 // natural column index (8 cols)
    const size_t base = (size_t)b * N * N;

    // init: tau = 1/acc[k-1] into swizzled smem; zero cp slices
    {
        float4 a0 = *(const float4*)&g_acc[k - 1][b * N + col];
        float4 a1 = *(const float4*)&g_acc[k - 1][b * N + col + 4];
        float4 t0 = {1.0f / a0.x, 1.0f / a0.y, 1.0f / a0.z, 1.0f / a0.w};
        float4 t1 = {1.0f / a1.x, 1.0f / a1.y, 1.0f / a1.z, 1.0f / a1.w};
        *(float4*)&s_tau[(64 * c + l) * 4]      = t0;
        *(float4*)&s_tau[(64 * c + 32 + l) * 4] = t1;
        float4 z = {0.f, 0.f, 0.f, 0.f};
        #pragma unroll
        for (int j = 0; j < 16; j++)
            *(float4*)&s_cp[tid * 64 + j * 4] = z;
    }
    __syncthreads();

    float* cpw = s_cp + wid * 2048;

    #pragma unroll 1
    for (int i = 0; i < RPW; i++) {
        const int row = rb * RPC + wid * RPW + i;
        const __half* rp = g_P + base + (size_t)row * N;
        uint4 q[8];
        #pragma unroll
        for (int cc = 0; cc < 8; cc++)
            q[cc] = *(const uint4*)(rp + cc * 256 + lane * 8);

        float dot = 0.0f;
        #pragma unroll
        for (int cc = 0; cc < 8; cc++) {
            const __half2* h = (const __half2*)&q[cc];
            float4 tA = *(const float4*)&s_tau[(64 * cc + lane) * 4];
            float4 tB = *(const float4*)&s_tau[(64 * cc + 32 + lane) * 4];
            float2 f0 = __half22float2(h[0]), f1 = __half22float2(h[1]);
            float2 f2 = __half22float2(h[2]), f3 = __half22float2(h[3]);
            dot = fmaf(f0.x, tA.x, dot); dot = fmaf(f0.y, tA.y, dot);
            dot = fmaf(f1.x, tA.z, dot); dot = fmaf(f1.y, tA.w, dot);
            dot = fmaf(f2.x, tB.x, dot); dot = fmaf(f2.y, tB.y, dot);
            dot = fmaf(f3.x, tB.z, dot); dot = fmaf(f3.y, tB.w, dot);
        }
        #pragma unroll
        for (int o = 16; o; o >>= 1) dot += __shfl_xor_sync(0xffffffffu, dot, o);
        const float s = 1.0f / dot;

        #pragma unroll
        for (int cc = 0; cc < 8; cc++) {
            const __half2* h = (const __half2*)&q[cc];
            float2 f0 = __half22float2(h[0]), f1 = __half22float2(h[1]);
            float2 f2 = __half22float2(h[2]), f3 = __half22float2(h[3]);
            float4 cA = *(const float4*)&cpw[(64 * cc + lane) * 4];
            float4 cB = *(const float4*)&cpw[(64 * cc + 32 + lane) * 4];
            cA.x = fmaf(f0.x, s, cA.x); cA.y = fmaf(f0.y, s, cA.y);
            cA.z = fmaf(f1.x, s, cA.z); cA.w = fmaf(f1.y, s, cA.w);
            cB.x = fmaf(f2.x, s, cB.x); cB.y = fmaf(f2.y, s, cB.y);
            cB.z = fmaf(f3.x, s, cB.z); cB.w = fmaf(f3.y, s, cB.w);
            *(float4*)&cpw[(64 * cc + lane) * 4]      = cA;
            *(float4*)&cpw[(64 * cc + 32 + lane) * 4] = cB;
        }
    }

    __syncthreads();
    // fold 8 warp slices and push to global accumulator
    float4 r0 = {0.f, 0.f, 0.f, 0.f}, r1 = {0.f, 0.f, 0.f, 0.f};
    #pragma unroll
    for (int w = 0; w < 8; w++) {
        const float* cw = s_cp + w * 2048;
        float4 x0 = *(const float4*)&cw[(64 * c + l) * 4];
        float4 x1 = *(const float4*)&cw[(64 * c + 32 + l) * 4];
        r0.x += x0.x; r0.y += x0.y; r0.z += x0.z; r0.w += x0.w;
        r1.x += x1.x; r1.y += x1.y; r1.z += x1.z; r1.w += x1.w;
    }
    float* acc = &g_acc[k][b * N + col];
    atomicAdd(acc + 0, r0.x); atomicAdd(acc + 1, r0.y);
    atomicAdd(acc + 2, r0.z); atomicAdd(acc + 3, r0.w);
    atomicAdd(acc + 4, r1.x); atomicAdd(acc + 5, r1.y);
    atomicAdd(acc + 6, r1.z); atomicAdd(acc + 7, r1.w);
}

// K10 = iteration 10 in fp32 from A: t9 = 1/(acc1*acc9); s10 -> g_s; acc10 = colsum(P0 s10)
__global__ void __launch_bounds__(TPB) k10_kernel(const float* __restrict__ A) {
    const int blk = blockIdx.x, b = blk / NBLK, rb = blk % NBLK;
    const int tid = threadIdx.x, wid = tid >> 5, lane = tid & 31;
    const int col = tid * 8;
    const size_t base = (size_t)b * N * N;
    __shared__ float red[2][8][2];

    const float* a1p = &g_acc[1][b * N + col];
    const float* a9p = &g_acc[9][b * N + col];
    float tv[8], cp[8] = {0, 0, 0, 0, 0, 0, 0, 0};
    #pragma unroll
    for (int j = 0; j < 8; j++) tv[j] = 1.0f / (a1p[j] * a9p[j]);   // absolute t^(9)

    #pragma unroll 1
    for (int p = 0; p < RPC / 2; p++) {
        const int r0 = rb * RPC + 2 * p;
        const float4* p0 = (const float4*)(A + base + (size_t)r0 * N + col);
        const float4* p1 = (const float4*)(A + base + (size_t)(r0 + 1) * N + col);
        float4 x0 = p0[0], x1 = p0[1], y0 = p1[0], y1 = p1[1];
        float a0[8] = {x0.x, x0.y, x0.z, x0.w, x1.x, x1.y, x1.z, x1.w};
        float a1[8] = {y0.x, y0.y, y0.z, y0.w, y1.x, y1.y, y1.z, y1.w};
        const float m0 = g_m[b * N + r0], m1 = g_m[b * N + r0 + 1];
        float e0[8], e1[8], l0 = 0.0f, l1 = 0.0f;
        #pragma unroll
        for (int k = 0; k < 8; k++) {
            e0[k] = __expf(fmaf(a0[k], INVL, -m0));
            e1[k] = __expf(fmaf(a1[k], INVL, -m1));
            l0 = fmaf(e0[k], tv[k], l0); l1 = fmaf(e1[k], tv[k], l1);
        }
        warp_red2(l0, l1);
        if (lane == 0) { red[p & 1][wid][0] = l0; red[p & 1][wid][1] = l1; }
        __syncthreads();
        l0 = red[p & 1][0][0]; l1 = red[p & 1][0][1];
        #pragma unroll
        for (int w = 1; w < 8; w++) { l0 += red[p & 1][w][0]; l1 += red[p & 1][w][1]; }
        const float s0 = 1.0f / l0, s1 = 1.0f / l1;   // s^(10)
        if (tid == 0) { g_s[b * N + r0] = s0; g_s[b * N + r0 + 1] = s1; }
        #pragma unroll
        for (int k = 0; k < 8; k++) {
            cp[k] = fmaf(e0[k], s0, cp[k]);
            cp[k] = fmaf(e1[k], s1, cp[k]);
        }
    }
    float* acc = &g_acc[NITER][b * N + col];
    #pragma unroll
    for (int k = 0; k < 8; k++) atomicAdd(acc + k, cp[k]);
}

// K11: out = exp(A*INVL - m_i) * s10_i * t10_j,  t10 = 1/acc10  (all fp32)
__global__ void __launch_bounds__(TPB) final_kernel(const float* __restrict__ A,
                                                    float* __restrict__ out) {
    const int rbase = blockIdx.x * 8;
    const int b = rbase >> 11;
    const int col = threadIdx.x * 8;
    const float* accp = &g_acc[NITER][b * N + col];
    float tv[8];
    #pragma unroll
    for (int j = 0; j < 8; j++) tv[j] = 1.0f / accp[j];

    #pragma unroll 1
    for (int r = 0; r < 8; r++) {
        const int row = rbase + r;
        const float s = g_s[row];
        const float m = g_m[row];
        const size_t off = (size_t)row * N + col;
        float4 x0 = *(const float4*)(A + off);
        float4 x1 = *(const float4*)(A + off + 4);
        float a[8] = {x0.x, x0.y, x0.z, x0.w, x1.x, x1.y, x1.z, x1.w};
        float4 o0, o1;
        o0.x = __expf(fmaf(a[0], INVL, -m)) * s * tv[0];
        o0.y = __expf(fmaf(a[1], INVL, -m)) * s * tv[1];
        o0.z = __expf(fmaf(a[2], INVL, -m)) * s * tv[2];
        o0.w = __expf(fmaf(a[3], INVL, -m)) * s * tv[3];
        o1.x = __expf(fmaf(a[4], INVL, -m)) * s * tv[4];
        o1.y = __expf(fmaf(a[5], INVL, -m)) * s * tv[5];
        o1.z = __expf(fmaf(a[6], INVL, -m)) * s * tv[6];
        o1.w = __expf(fmaf(a[7], INVL, -m)) * s * tv[7];
        *(float4*)(out + off) = o0;
        *(float4*)(out + off + 4) = o1;
    }
}

extern "C" void kernel_launch(void* const* d_in, const int* in_sizes, int n_in,
                              void* d_out, int out_size) {
    const float* A = (const float*)d_in[0];
    float* O = (float*)d_out;

    cudaFuncSetAttribute(iter_kernel, cudaFuncAttributeMaxDynamicSharedMemorySize, ITER_SMEM);

    zero_kernel<<<(NITER * BATCH * N) / TPB, TPB>>>();
    k1_kernel<<<GRID_BIG, TPB>>>(A);
    k2_kernel<<<GRID_BIG, TPB>>>(A);
    for (int k = 3; k <= NITER - 1; k++)
        iter_kernel<<<GRID_BIG, TPB, ITER_SMEM>>>(k);
    k10_kernel<<<GRID_BIG, TPB>>>(A);
    final_kernel<<<(BATCH * N) / 8, TPB>>>(A, O);
}

// round 6
// speedup vs baseline: 1.4450x; 1.4450x over previous
#include <cuda_runtime.h>
#include <cuda_fp16.h>
#include <math.h>
#include <stdint.h>

#define BATCH 8
#define N     2048
#define TPB   256
#define RPC   32                    // rows per CTA in big kernels
#define NBLK  (N / RPC)             // 64
#define GRID_BIG (BATCH * NBLK)     // 512
#define INVL  20.0f                 // 1/lambda
#define NITER 10

#define TR        4                       // rows per bulk-copy tile (iter kernel)
#define TILE_B    (TR * N * 2)            // 16384 bytes (fp16 rows)
#define NROUND    (RPC / TR)              // 8 rounds per CTA
#define ITER_SMEM (2 * TILE_B + 256)      // 2 stages + red + mbars

// scratch (__device__ globals; no allocation allowed)
__device__ __half g_P[(size_t)BATCH * N * N];    // 67 MB: Q = fp16(P0 * s2 * t1)
__device__ float  g_m[BATCH * N];                // row maxes of A*INVL
__device__ float  g_s[BATCH * N];                // s^(10)
__device__ float  g_acc[NITER + 1][BATCH * N];   // column accumulators per iteration

__global__ void zero_kernel() {
    int idx = blockIdx.x * TPB + threadIdx.x;    // zero acc[1..10]
    (&g_acc[1][0])[idx] = 0.0f;
}

__device__ __forceinline__ uint32_t smem_u32(const void* p) {
    uint32_t a;
    asm("{ .reg .u64 t; cvta.to.shared.u64 t, %1; cvt.u32.u64 %0, t; }" : "=r"(a) : "l"(p));
    return a;
}
__device__ __forceinline__ uint64_t gmem_u64(const void* p) {
    uint64_t a;
    asm("cvta.to.global.u64 %0, %1;" : "=l"(a) : "l"(p));
    return a;
}
__device__ __forceinline__ void mbar_init(uint32_t mbar, uint32_t cnt) {
    asm volatile("mbarrier.init.shared.b64 [%0], %1;" :: "r"(mbar), "r"(cnt) : "memory");
}
__device__ __forceinline__ void mbar_expect_tx(uint32_t mbar, uint32_t bytes) {
    asm volatile("mbarrier.arrive.expect_tx.shared.b64 _, [%0], %1;"
                 :: "r"(mbar), "r"(bytes) : "memory");
}
__device__ __forceinline__ void bulk_g2s(uint32_t dst_smem, uint64_t src_gmem,
                                         uint32_t bytes, uint32_t mbar) {
    asm volatile("cp.async.bulk.shared::cta.global.mbarrier::complete_tx::bytes "
                 "[%0], [%1], %2, [%3];"
                 :: "r"(dst_smem), "l"(src_gmem), "r"(bytes), "r"(mbar) : "memory");
}
__device__ __forceinline__ void mbar_wait(uint32_t mbar, uint32_t parity) {
    uint32_t done;
    asm volatile("{\n\t.reg .pred p;\n\t"
                 "mbarrier.try_wait.parity.acquire.cta.shared::cta.b64 p, [%1], %2;\n\t"
                 "selp.b32 %0, 1, 0, p;\n\t}"
                 : "=r"(done) : "r"(mbar), "r"(parity) : "memory");
    if (!done) {
        asm volatile("{\n\t.reg .pred P1;\n\t"
                     "WL_%=:\n\t"
                     "mbarrier.try_wait.parity.acquire.cta.shared::cta.b64 P1, [%0], %1, 0x989680;\n\t"
                     "@P1 bra.uni WD_%=;\n\t"
                     "bra.uni WL_%=;\n\t"
                     "WD_%=:\n\t}"
                     :: "r"(mbar), "r"(parity) : "memory");
    }
}

__device__ __forceinline__ void warp_red2(float& l0, float& l1) {
    #pragma unroll
    for (int o = 16; o; o >>= 1) {
        l0 += __shfl_xor_sync(0xffffffffu, l0, o);
        l1 += __shfl_xor_sync(0xffffffffu, l1, o);
    }
}

// K1 = iteration 1 (fp32 from A): m_i = rowmax; s1 = 1/rowsum(P0); acc1 = colsum(P0 s1)
__global__ void __launch_bounds__(TPB) k1_kernel(const float* __restrict__ A) {
    const int blk = blockIdx.x, b = blk / NBLK, rb = blk % NBLK;
    const int tid = threadIdx.x, wid = tid >> 5, lane = tid & 31;
    const int col = tid * 8;
    const size_t base = (size_t)b * N * N;
    __shared__ float redA[8][2], redB[8][2];
    float cp[8] = {0, 0, 0, 0, 0, 0, 0, 0};

    #pragma unroll 1
    for (int p = 0; p < RPC / 2; p++) {
        const int r0 = rb * RPC + 2 * p;
        const float4* a0p = (const float4*)(A + base + (size_t)r0 * N + col);
        const float4* a1p = (const float4*)(A + base + (size_t)(r0 + 1) * N + col);
        float4 x0 = a0p[0], x1 = a0p[1], y0 = a1p[0], y1 = a1p[1];
        float a0[8] = {x0.x, x0.y, x0.z, x0.w, x1.x, x1.y, x1.z, x1.w};
        float a1[8] = {y0.x, y0.y, y0.z, y0.w, y1.x, y1.y, y1.z, y1.w};
        float m0 = -INFINITY, m1 = -INFINITY;
        #pragma unroll
        for (int k = 0; k < 8; k++) {
            a0[k] *= INVL; a1[k] *= INVL;
            m0 = fmaxf(m0, a0[k]); m1 = fmaxf(m1, a1[k]);
        }
        #pragma unroll
        for (int o = 16; o; o >>= 1) {
            m0 = fmaxf(m0, __shfl_xor_sync(0xffffffffu, m0, o));
            m1 = fmaxf(m1, __shfl_xor_sync(0xffffffffu, m1, o));
        }
        if (lane == 0) { redA[wid][0] = m0; redA[wid][1] = m1; }
        __syncthreads();
        m0 = redA[0][0]; m1 = redA[0][1];
        #pragma unroll
        for (int w = 1; w < 8; w++) { m0 = fmaxf(m0, redA[w][0]); m1 = fmaxf(m1, redA[w][1]); }

        float e0[8], e1[8], l0 = 0.0f, l1 = 0.0f;
        #pragma unroll
        for (int k = 0; k < 8; k++) {
            e0[k] = __expf(a0[k] - m0); e1[k] = __expf(a1[k] - m1);
            l0 += e0[k]; l1 += e1[k];
        }
        warp_red2(l0, l1);
        if (lane == 0) { redB[wid][0] = l0; redB[wid][1] = l1; }
        __syncthreads();
        l0 = redB[0][0]; l1 = redB[0][1];
        #pragma unroll
        for (int w = 1; w < 8; w++) { l0 += redB[w][0]; l1 += redB[w][1]; }
        const float s0 = 1.0f / l0, s1 = 1.0f / l1;
        if (tid == 0) { g_m[b * N + r0] = m0; g_m[b * N + r0 + 1] = m1; }
        #pragma unroll
        for (int k = 0; k < 8; k++) {
            cp[k] = fmaf(e0[k], s0, cp[k]);
            cp[k] = fmaf(e1[k], s1, cp[k]);
        }
    }
    float* acc = &g_acc[1][b * N + col];
    #pragma unroll
    for (int k = 0; k < 8; k++) atomicAdd(acc + k, cp[k]);
}

// K2 = iteration 2 (fp32 from A) + write Q = fp16(P0 s2 t1); acc2 = colsum(Q)
__global__ void __launch_bounds__(TPB) k2_kernel(const float* __restrict__ A) {
    const int blk = blockIdx.x, b = blk / NBLK, rb = blk % NBLK;
    const int tid = threadIdx.x, wid = tid >> 5, lane = tid & 31;
    const int col = tid * 8;
    const size_t base = (size_t)b * N * N;
    __shared__ float red[2][8][2];

    const float* a1p = &g_acc[1][b * N + col];
    float tv[8], cp[8] = {0, 0, 0, 0, 0, 0, 0, 0};
    #pragma unroll
    for (int j = 0; j < 8; j++) tv[j] = 1.0f / a1p[j];

    #pragma unroll 1
    for (int p = 0; p < RPC / 2; p++) {
        const int r0 = rb * RPC + 2 * p;
        const float4* p0 = (const float4*)(A + base + (size_t)r0 * N + col);
        const float4* p1 = (const float4*)(A + base + (size_t)(r0 + 1) * N + col);
        float4 x0 = p0[0], x1 = p0[1], y0 = p1[0], y1 = p1[1];
        float a0[8] = {x0.x, x0.y, x0.z, x0.w, x1.x, x1.y, x1.z, x1.w};
        float a1[8] = {y0.x, y0.y, y0.z, y0.w, y1.x, y1.y, y1.z, y1.w};
        const float m0 = g_m[b * N + r0], m1 = g_m[b * N + r0 + 1];
        float e0[8], e1[8], l0 = 0.0f, l1 = 0.0f;
        #pragma unroll
        for (int k = 0; k < 8; k++) {
            e0[k] = __expf(fmaf(a0[k], INVL, -m0)) * tv[k];   // P0 * t1
            e1[k] = __expf(fmaf(a1[k], INVL, -m1)) * tv[k];
            l0 += e0[k]; l1 += e1[k];
        }
        warp_red2(l0, l1);
        if (lane == 0) { red[p & 1][wid][0] = l0; red[p & 1][wid][1] = l1; }
        __syncthreads();
        l0 = red[p & 1][0][0]; l1 = red[p & 1][0][1];
        #pragma unroll
        for (int w = 1; w < 8; w++) { l0 += red[p & 1][w][0]; l1 += red[p & 1][w][1]; }
        const float s0 = 1.0f / l0, s1 = 1.0f / l1;   // s2 rows

        float q0[8], q1[8];
        #pragma unroll
        for (int k = 0; k < 8; k++) {
            q0[k] = e0[k] * s0;  q1[k] = e1[k] * s1;   // Q entries (row sums == 1)
            cp[k] += q0[k] + q1[k];
        }
        uint4 w0, w1;
        __half2* h0 = reinterpret_cast<__half2*>(&w0);
        __half2* h1 = reinterpret_cast<__half2*>(&w1);
        #pragma unroll
        for (int j = 0; j < 4; j++) {
            h0[j] = __floats2half2_rn(q0[2 * j], q0[2 * j + 1]);
            h1[j] = __floats2half2_rn(q1[2 * j], q1[2 * j + 1]);
        }
        *(uint4*)(g_P + base + (size_t)r0 * N + col) = w0;
        *(uint4*)(g_P + base + (size_t)(r0 + 1) * N + col) = w1;
    }
    float* acc = &g_acc[2][b * N + col];
    #pragma unroll
    for (int k = 0; k < 8; k++) atomicAdd(acc + k, cp[k]);
}

// K3..K9 on fp16 Q: cp.async.bulk double-buffered tiles (4 rows = 16 KB) -> smem,
// LDS.128 reads, register cp partials.  tau = 1/acc[k-1]; acc[k] = colsum(Q sigma)
__global__ void __launch_bounds__(TPB, 4) iter_kernel(int k) {
    extern __shared__ __align__(128) unsigned char smraw[];
    __half* tiles = reinterpret_cast<__half*>(smraw);                 // 2 x TILE_B
    float*  red   = reinterpret_cast<float*>(smraw + 2 * TILE_B);     // 8 warps x TR
    uint64_t* mbar = reinterpret_cast<uint64_t*>(smraw + 2 * TILE_B + 128);

    const int blk = blockIdx.x, b = blk / NBLK, rb = blk % NBLK;
    const int tid = threadIdx.x, wid = tid >> 5, lane = tid & 31;
    const int col = tid * 8;
    const size_t base = (size_t)b * N * N;

    const uint32_t sm_tiles = smem_u32(tiles);
    const uint32_t sm_mbar0 = smem_u32(mbar);
    const uint32_t sm_mbar1 = sm_mbar0 + 8;

    float tv[8], cp[8] = {0, 0, 0, 0, 0, 0, 0, 0};
    {
        float4 a0 = *(const float4*)&g_acc[k - 1][b * N + col];
        float4 a1 = *(const float4*)&g_acc[k - 1][b * N + col + 4];
        tv[0] = 1.0f / a0.x; tv[1] = 1.0f / a0.y; tv[2] = 1.0f / a0.z; tv[3] = 1.0f / a0.w;
        tv[4] = 1.0f / a1.x; tv[5] = 1.0f / a1.y; tv[6] = 1.0f / a1.z; tv[7] = 1.0f / a1.w;
    }

    if (tid == 0) { mbar_init(sm_mbar0, 1); mbar_init(sm_mbar1, 1); }
    __syncthreads();

    const uint64_t gsrc = gmem_u64(g_P + base + (size_t)rb * RPC * N);
    if (tid == 0) {
        mbar_expect_tx(sm_mbar0, TILE_B);
        bulk_g2s(sm_tiles, gsrc, TILE_B, sm_mbar0);
    }

    #pragma unroll 1
    for (int t = 0; t < NROUND; t++) {
        // issue next tile (stage was released by the barrier at the end of round t-1)
        // NOTE: stage stride is TILE_B BYTES (sm_tiles is a byte address) — R5 bug was /2
        if (t + 1 < NROUND && tid == 0) {
            const uint32_t mb = ((t + 1) & 1) ? sm_mbar1 : sm_mbar0;
            mbar_expect_tx(mb, TILE_B);
            bulk_g2s(sm_tiles + ((t + 1) & 1) * TILE_B,
                     gsrc + (uint64_t)(t + 1) * TILE_B, TILE_B, mb);
        }
        mbar_wait((t & 1) ? sm_mbar1 : sm_mbar0, (t >> 1) & 1);

        const uint32_t stage = sm_tiles + (t & 1) * TILE_B + tid * 16;
        uint4 q[TR];
        float d[TR];
        #pragma unroll
        for (int r = 0; r < TR; r++) {
            asm volatile("ld.shared.v4.u32 {%0,%1,%2,%3}, [%4];"
                         : "=r"(q[r].x), "=r"(q[r].y), "=r"(q[r].z), "=r"(q[r].w)
                         : "r"(stage + r * (N * 2)));
            const __half2* h = (const __half2*)&q[r];
            float2 f0 = __half22float2(h[0]), f1 = __half22float2(h[1]);
            float2 f2 = __half22float2(h[2]), f3 = __half22float2(h[3]);
            float dd = 0.0f;
            dd = fmaf(f0.x, tv[0], dd); dd = fmaf(f0.y, tv[1], dd);
            dd = fmaf(f1.x, tv[2], dd); dd = fmaf(f1.y, tv[3], dd);
            dd = fmaf(f2.x, tv[4], dd); dd = fmaf(f2.y, tv[5], dd);
            dd = fmaf(f3.x, tv[6], dd); dd = fmaf(f3.y, tv[7], dd);
            d[r] = dd;
        }
        #pragma unroll
        for (int o = 16; o; o >>= 1) {
            #pragma unroll
            for (int r = 0; r < TR; r++)
                d[r] += __shfl_xor_sync(0xffffffffu, d[r], o);
        }
        if (lane == 0) {
            #pragma unroll
            for (int r = 0; r < TR; r++) red[wid * TR + r] = d[r];
        }
        __syncthreads();
        float s[TR];
        #pragma unroll
        for (int r = 0; r < TR; r++) {
            float acc = red[r];
            #pragma unroll
            for (int w = 1; w < 8; w++) acc += red[w * TR + r];
            s[r] = 1.0f / acc;
        }
        #pragma unroll
        for (int r = 0; r < TR; r++) {
            const __half2* h = (const __half2*)&q[r];
            float2 f0 = __half22float2(h[0]), f1 = __half22float2(h[1]);
            float2 f2 = __half22float2(h[2]), f3 = __half22float2(h[3]);
            cp[0] = fmaf(f0.x, s[r], cp[0]); cp[1] = fmaf(f0.y, s[r], cp[1]);
            cp[2] = fmaf(f1.x, s[r], cp[2]); cp[3] = fmaf(f1.y, s[r], cp[3]);
            cp[4] = fmaf(f2.x, s[r], cp[4]); cp[5] = fmaf(f2.y, s[r], cp[5]);
            cp[6] = fmaf(f3.x, s[r], cp[6]); cp[7] = fmaf(f3.y, s[r], cp[7]);
        }
        __syncthreads();   // releases stage (t&1) for the round-(t+2) issue; protects red[]
    }

    float* acc = &g_acc[k][b * N + col];
    #pragma unroll
    for (int j = 0; j < 8; j++) atomicAdd(acc + j, cp[j]);
}

// K10 = iteration 10 in fp32 from A: t9 = 1/(acc1*acc9); s10 -> g_s; acc10 = colsum(P0 s10)
__global__ void __launch_bounds__(TPB) k10_kernel(const float* __restrict__ A) {
    const int blk = blockIdx.x, b = blk / NBLK, rb = blk % NBLK;
    const int tid = threadIdx.x, wid = tid >> 5, lane = tid & 31;
    const int col = tid * 8;
    const size_t base = (size_t)b * N * N;
    __shared__ float red[2][8][2];

    const float* a1p = &g_acc[1][b * N + col];
    const float* a9p = &g_acc[9][b * N + col];
    float tv[8], cp[8] = {0, 0, 0, 0, 0, 0, 0, 0};
    #pragma unroll
    for (int j = 0; j < 8; j++) tv[j] = 1.0f / (a1p[j] * a9p[j]);   // absolute t^(9)

    #pragma unroll 1
    for (int p = 0; p < RPC / 2; p++) {
        const int r0 = rb * RPC + 2 * p;
        const float4* p0 = (const float4*)(A + base + (size_t)r0 * N + col);
        const float4* p1 = (const float4*)(A + base + (size_t)(r0 + 1) * N + col);
        float4 x0 = p0[0], x1 = p0[1], y0 = p1[0], y1 = p1[1];
        float a0[8] = {x0.x, x0.y, x0.z, x0.w, x1.x, x1.y, x1.z, x1.w};
        float a1[8] = {y0.x, y0.y, y0.z, y0.w, y1.x, y1.y, y1.z, y1.w};
        const float m0 = g_m[b * N + r0], m1 = g_m[b * N + r0 + 1];
        float e0[8], e1[8], l0 = 0.0f, l1 = 0.0f;
        #pragma unroll
        for (int k = 0; k < 8; k++) {
            e0[k] = __expf(fmaf(a0[k], INVL, -m0));
            e1[k] = __expf(fmaf(a1[k], INVL, -m1));
            l0 = fmaf(e0[k], tv[k], l0); l1 = fmaf(e1[k], tv[k], l1);
        }
        warp_red2(l0, l1);
        if (lane == 0) { red[p & 1][wid][0] = l0; red[p & 1][wid][1] = l1; }
        __syncthreads();
        l0 = red[p & 1][0][0]; l1 = red[p & 1][0][1];
        #pragma unroll
        for (int w = 1; w < 8; w++) { l0 += red[p & 1][w][0]; l1 += red[p & 1][w][1]; }
        const float s0 = 1.0f / l0, s1 = 1.0f / l1;   // s^(10)
        if (tid == 0) { g_s[b * N + r0] = s0; g_s[b * N + r0 + 1] = s1; }
        #pragma unroll
        for (int k = 0; k < 8; k++) {
            cp[k] = fmaf(e0[k], s0, cp[k]);
            cp[k] = fmaf(e1[k], s1, cp[k]);
        }
    }
    float* acc = &g_acc[NITER][b * N + col];
    #pragma unroll
    for (int k = 0; k < 8; k++) atomicAdd(acc + k, cp[k]);
}

// K11: out = exp(A*INVL - m_i) * s10_i * t10_j,  t10 = 1/acc10  (all fp32)
__global__ void __launch_bounds__(TPB) final_kernel(const float* __restrict__ A,
                                                    float* __restrict__ out) {
    const int rbase = blockIdx.x * 8;
    const int b = rbase >> 11;
    const int col = threadIdx.x * 8;
    const float* accp = &g_acc[NITER][b * N + col];
    float tv[8];
    #pragma unroll
    for (int j = 0; j < 8; j++) tv[j] = 1.0f / accp[j];

    #pragma unroll 1
    for (int r = 0; r < 8; r++) {
        const int row = rbase + r;
        const float s = g_s[row];
        const float m = g_m[row];
        const size_t off = (size_t)row * N + col;
        float4 x0 = *(const float4*)(A + off);
        float4 x1 = *(const float4*)(A + off + 4);
        float a[8] = {x0.x, x0.y, x0.z, x0.w, x1.x, x1.y, x1.z, x1.w};
        float4 o0, o1;
        o0.x = __expf(fmaf(a[0], INVL, -m)) * s * tv[0];
        o0.y = __expf(fmaf(a[1], INVL, -m)) * s * tv[1];
        o0.z = __expf(fmaf(a[2], INVL, -m)) * s * tv[2];
        o0.w = __expf(fmaf(a[3], INVL, -m)) * s * tv[3];
        o1.x = __expf(fmaf(a[4], INVL, -m)) * s * tv[4];
        o1.y = __expf(fmaf(a[5], INVL, -m)) * s * tv[5];
        o1.z = __expf(fmaf(a[6], INVL, -m)) * s * tv[6];
        o1.w = __expf(fmaf(a[7], INVL, -m)) * s * tv[7];
        *(float4*)(out + off) = o0;
        *(float4*)(out + off + 4) = o1;
    }
}

extern "C" void kernel_launch(void* const* d_in, const int* in_sizes, int n_in,
                              void* d_out, int out_size) {
    const float* A = (const float*)d_in[0];
    float* O = (float*)d_out;

    zero_kernel<<<(NITER * BATCH * N) / TPB, TPB>>>();
    k1_kernel<<<GRID_BIG, TPB>>>(A);
    k2_kernel<<<GRID_BIG, TPB>>>(A);
    for (int k = 3; k <= NITER - 1; k++)
        iter_kernel<<<GRID_BIG, TPB, ITER_SMEM>>>(k);
    k10_kernel<<<GRID_BIG, TPB>>>(A);
    final_kernel<<<(BATCH * N) / 8, TPB>>>(A, O);
}

// round 8
// speedup vs baseline: 2.0147x; 1.3943x over previous
#include <cuda_runtime.h>
#include <math.h>
#include <stdint.h>

#define BATCH 8
#define N     2048
#define TPB   256
#define RPC   32
#define NBLK  (N / RPC)             // 64
#define GRID_BIG (BATCH * NBLK)     // 512
#define INVL  20.0f
#define NITER 10

#define CAP   320                   // sparse slots per row (worst flat row ~250)
#define NSLOT (CAP / 32)            // 10 per lane
#define CUT   1.879529e-12f         // e^-27: keep entries with exp(20(a-m)) > CUT
#define NROWS (BATCH * N)           // 16384

// scratch (__device__ globals; no allocation allowed)
__device__ float g_m[NROWS];                 // row maxes of A*INVL
__device__ float g_s[NROWS];                 // s^(10)
__device__ float g_acc[NITER + 1][NROWS];    // column accumulators per iteration (abs potentials)
__device__ int   g_scols[(size_t)NROWS * CAP];
__device__ float g_svals[(size_t)NROWS * CAP];
__device__ int   g_scnt[NROWS];

__global__ void zero_kernel() {
    int idx = blockIdx.x * TPB + threadIdx.x;
    if (idx < NITER * NROWS) (&g_acc[1][0])[idx] = 0.0f;
    else if (idx < NITER * NROWS + NROWS) g_scnt[idx - NITER * NROWS] = 0;
}

__device__ __forceinline__ void warp_red2(float& l0, float& l1) {
    #pragma unroll
    for (int o = 16; o; o >>= 1) {
        l0 += __shfl_xor_sync(0xffffffffu, l0, o);
        l1 += __shfl_xor_sync(0xffffffffu, l1, o);
    }
}

// K1 = iteration 1 (fp32 from A): m_i = rowmax; s1 = 1/rowsum(P0); acc1 = dense colsum(P0 s1);
// ALSO extracts sparse lists: entries with exp(20(a-m)) > CUT.
__global__ void __launch_bounds__(TPB) k1_kernel(const float* __restrict__ A) {
    const int blk = blockIdx.x, b = blk / NBLK, rb = blk % NBLK;
    const int tid = threadIdx.x, wid = tid >> 5, lane = tid & 31;
    const int col = tid * 8;
    const size_t base = (size_t)b * N * N;
    __shared__ float redA[8][2], redB[8][2];
    __shared__ int scnt_sm[RPC];
    if (tid < RPC) scnt_sm[tid] = 0;
    float cp[8] = {0, 0, 0, 0, 0, 0, 0, 0};

    #pragma unroll 1
    for (int p = 0; p < RPC / 2; p++) {
        const int r0 = rb * RPC + 2 * p;
        const float4* a0p = (const float4*)(A + base + (size_t)r0 * N + col);
        const float4* a1p = (const float4*)(A + base + (size_t)(r0 + 1) * N + col);
        float4 x0 = a0p[0], x1 = a0p[1], y0 = a1p[0], y1 = a1p[1];
        float a0[8] = {x0.x, x0.y, x0.z, x0.w, x1.x, x1.y, x1.z, x1.w};
        float a1[8] = {y0.x, y0.y, y0.z, y0.w, y1.x, y1.y, y1.z, y1.w};
        float m0 = -INFINITY, m1 = -INFINITY;
        #pragma unroll
        for (int k = 0; k < 8; k++) {
            a0[k] *= INVL; a1[k] *= INVL;
            m0 = fmaxf(m0, a0[k]); m1 = fmaxf(m1, a1[k]);
        }
        #pragma unroll
        for (int o = 16; o; o >>= 1) {
            m0 = fmaxf(m0, __shfl_xor_sync(0xffffffffu, m0, o));
            m1 = fmaxf(m1, __shfl_xor_sync(0xffffffffu, m1, o));
        }
        if (lane == 0) { redA[wid][0] = m0; redA[wid][1] = m1; }
        __syncthreads();
        m0 = redA[0][0]; m1 = redA[0][1];
        #pragma unroll
        for (int w = 1; w < 8; w++) { m0 = fmaxf(m0, redA[w][0]); m1 = fmaxf(m1, redA[w][1]); }

        float e0[8], e1[8], l0 = 0.0f, l1 = 0.0f;
        #pragma unroll
        for (int k = 0; k < 8; k++) {
            e0[k] = __expf(a0[k] - m0); e1[k] = __expf(a1[k] - m1);
            l0 += e0[k]; l1 += e1[k];
        }

        // sparse extraction (counters are per-row -> no race across rounds)
        const size_t rid0 = (size_t)(b * N + r0);
        #pragma unroll
        for (int k = 0; k < 8; k++) {
            if (e0[k] > CUT) {
                int idx = atomicAdd(&scnt_sm[2 * p], 1);
                if (idx < CAP) {
                    g_scols[rid0 * CAP + idx] = col + k;
                    g_svals[rid0 * CAP + idx] = e0[k];
                }
            }
            if (e1[k] > CUT) {
                int idx = atomicAdd(&scnt_sm[2 * p + 1], 1);
                if (idx < CAP) {
                    g_scols[(rid0 + 1) * CAP + idx] = col + k;
                    g_svals[(rid0 + 1) * CAP + idx] = e1[k];
                }
            }
        }

        warp_red2(l0, l1);
        if (lane == 0) { redB[wid][0] = l0; redB[wid][1] = l1; }
        __syncthreads();
        l0 = redB[0][0]; l1 = redB[0][1];
        #pragma unroll
        for (int w = 1; w < 8; w++) { l0 += redB[w][0]; l1 += redB[w][1]; }
        const float s0 = 1.0f / l0, s1 = 1.0f / l1;
        if (tid == 0) { g_m[b * N + r0] = m0; g_m[b * N + r0 + 1] = m1; }
        #pragma unroll
        for (int k = 0; k < 8; k++) {
            cp[k] = fmaf(e0[k], s0, cp[k]);
            cp[k] = fmaf(e1[k], s1, cp[k]);
        }
    }
    float* acc = &g_acc[1][b * N + col];
    #pragma unroll
    for (int k = 0; k < 8; k++) atomicAdd(acc + k, cp[k]);

    __syncthreads();
    if (tid < RPC)
        g_scnt[b * N + rb * RPC + tid] = min(scnt_sm[tid], CAP);
}

// K2..K9 sparse: one warp per row. tau = 1/acc[k-1]; sigma = 1/sum(val*tau);
// acc[k][col] += val*sigma.  (vals are fp32 P0 entries — no quantization)
__global__ void __launch_bounds__(TPB) sparse_iter(int k) {
    const int wid = threadIdx.x >> 5, lane = threadIdx.x & 31;
    const int rid = blockIdx.x * 8 + wid;            // 0..NROWS-1
    const int b = rid >> 11;
    const int cnt = g_scnt[rid];
    const float* __restrict__ accp = &g_acc[k - 1][b * N];
    float* accn = &g_acc[k][b * N];
    const size_t base = (size_t)rid * CAP;

    int cols[NSLOT];
    float vals[NSLOT];
    float dot = 0.0f;
    #pragma unroll
    for (int u = 0; u < NSLOT; u++) {
        const int s = lane + 32 * u;
        const bool ok = s < cnt;
        cols[u] = ok ? g_scols[base + s] : 0;
        vals[u] = ok ? g_svals[base + s] : 0.0f;
        if (ok) {
            float a = accp[cols[u]];
            dot += vals[u] * (1.0f / fmaxf(a, 1e-30f));
        }
    }
    #pragma unroll
    for (int o = 16; o; o >>= 1) dot += __shfl_xor_sync(0xffffffffu, dot, o);
    const float sig = 1.0f / dot;
    #pragma unroll
    for (int u = 0; u < NSLOT; u++)
        if (lane + 32 * u < cnt) atomicAdd(accn + cols[u], vals[u] * sig);
}

// K10 = iteration 10 dense fp32 from A: t9 = 1/acc9; s10 -> g_s; acc10 = dense colsum(P0 s10)
__global__ void __launch_bounds__(TPB) k10_kernel(const float* __restrict__ A) {
    const int blk = blockIdx.x, b = blk / NBLK, rb = blk % NBLK;
    const int tid = threadIdx.x, wid = tid >> 5, lane = tid & 31;
    const int col = tid * 8;
    const size_t base = (size_t)b * N * N;
    __shared__ float red[2][8][2];

    const float* a9p = &g_acc[9][b * N + col];
    float tv[8], cp[8] = {0, 0, 0, 0, 0, 0, 0, 0};
    #pragma unroll
    for (int j = 0; j < 8; j++) tv[j] = 1.0f / fmaxf(a9p[j], 1e-30f);   // absolute t^(9)

    #pragma unroll 1
    for (int p = 0; p < RPC / 2; p++) {
        const int r0 = rb * RPC + 2 * p;
        const float4* p0 = (const float4*)(A + base + (size_t)r0 * N + col);
        const float4* p1 = (const float4*)(A + base + (size_t)(r0 + 1) * N + col);
        float4 x0 = p0[0], x1 = p0[1], y0 = p1[0], y1 = p1[1];
        float a0[8] = {x0.x, x0.y, x0.z, x0.w, x1.x, x1.y, x1.z, x1.w};
        float a1[8] = {y0.x, y0.y, y0.z, y0.w, y1.x, y1.y, y1.z, y1.w};
        const float m0 = g_m[b * N + r0], m1 = g_m[b * N + r0 + 1];
        float e0[8], e1[8], l0 = 0.0f, l1 = 0.0f;
        #pragma unroll
        for (int k = 0; k < 8; k++) {
            e0[k] = __expf(fmaf(a0[k], INVL, -m0));
            e1[k] = __expf(fmaf(a1[k], INVL, -m1));
            l0 = fmaf(e0[k], tv[k], l0); l1 = fmaf(e1[k], tv[k], l1);
        }
        warp_red2(l0, l1);
        if (lane == 0) { red[p & 1][wid][0] = l0; red[p & 1][wid][1] = l1; }
        __syncthreads();
        l0 = red[p & 1][0][0]; l1 = red[p & 1][0][1];
        #pragma unroll
        for (int w = 1; w < 8; w++) { l0 += red[p & 1][w][0]; l1 += red[p & 1][w][1]; }
        const float s0 = 1.0f / l0, s1 = 1.0f / l1;   // s^(10)
        if (tid == 0) { g_s[b * N + r0] = s0; g_s[b * N + r0 + 1] = s1; }
        #pragma unroll
        for (int k = 0; k < 8; k++) {
            cp[k] = fmaf(e0[k], s0, cp[k]);
            cp[k] = fmaf(e1[k], s1, cp[k]);
        }
    }
    float* acc = &g_acc[NITER][b * N + col];
    #pragma unroll
    for (int k = 0; k < 8; k++) atomicAdd(acc + k, cp[k]);
}

// K11: out = exp(A*INVL - m_i) * s10_i * t10_j,  t10 = 1/acc10  (all fp32)
__global__ void __launch_bounds__(TPB) final_kernel(const float* __restrict__ A,
                                                    float* __restrict__ out) {
    const int rbase = blockIdx.x * 8;
    const int b = rbase >> 11;
    const int col = threadIdx.x * 8;
    const float* accp = &g_acc[NITER][b * N + col];
    float tv[8];
    #pragma unroll
    for (int j = 0; j < 8; j++) tv[j] = 1.0f / accp[j];

    #pragma unroll 1
    for (int r = 0; r < 8; r++) {
        const int row = rbase + r;
        const float s = g_s[row];
        const float m = g_m[row];
        const size_t off = (size_t)row * N + col;
        float4 x0 = *(const float4*)(A + off);
        float4 x1 = *(const float4*)(A + off + 4);
        float a[8] = {x0.x, x0.y, x0.z, x0.w, x1.x, x1.y, x1.z, x1.w};
        float4 o0, o1;
        o0.x = __expf(fmaf(a[0], INVL, -m)) * s * tv[0];
        o0.y = __expf(fmaf(a[1], INVL, -m)) * s * tv[1];
        o0.z = __expf(fmaf(a[2], INVL, -m)) * s * tv[2];
        o0.w = __expf(fmaf(a[3], INVL, -m)) * s * tv[3];
        o1.x = __expf(fmaf(a[4], INVL, -m)) * s * tv[4];
        o1.y = __expf(fmaf(a[5], INVL, -m)) * s * tv[5];
        o1.z = __expf(fmaf(a[6], INVL, -m)) * s * tv[6];
        o1.w = __expf(fmaf(a[7], INVL, -m)) * s * tv[7];
        *(float4*)(out + off) = o0;
        *(float4*)(out + off + 4) = o1;
    }
}

extern "C" void kernel_launch(void* const* d_in, const int* in_sizes, int n_in,
                              void* d_out, int out_size) {
    const float* A = (const float*)d_in[0];
    float* O = (float*)d_out;

    const int zgrid = (NITER * NROWS + NROWS + TPB - 1) / TPB;
    zero_kernel<<<zgrid, TPB>>>();
    k1_kernel<<<GRID_BIG, TPB>>>(A);
    for (int k = 2; k <= NITER - 1; k++)
        sparse_iter<<<NROWS / 8, TPB>>>(k);
    k10_kernel<<<GRID_BIG, TPB>>>(A);
    final_kernel<<<(BATCH * N) / 8, TPB>>>(A, O);
}